// round 9
// baseline (speedup 1.0000x reference)
#include <cuda_runtime.h>
#include <math.h>

// ---------------- problem constants ----------------
#define TT 512
#define BB 64
#define II 256
#define HH 1024
#define AA 128
#define OO 1024
#define PSZ0 13568            // I + 13H
#define PSZ1 14336            // H + 13O
#define NB 256                // persistent CTAs: 2/SM on 128 SMs -> safe on 148/152-SM parts
#define BIGB (1 << 30)
#define OFFA (64 * PSZ1)      // stride between the two ahe partial buffers

// ---------------- device scratch (static, no runtime alloc) ----------------
__device__ float g_partF[20 * 64 * 4096];   // fcell split-K partials (S3: 20, S6: 16)
__device__ float g_partA[48 * 64 * 512];    // adapt split-K partials (S1: 48, S4: 36)
__device__ float g_aheP [2 * 64 * PSZ1];    // policy output as 2 K-partials (summed by consumers)
__device__ float g_a0x[BB * AA];
__device__ float g_a0c[BB * AA];
__device__ float g_a1x[BB * AA];
__device__ float g_a1c[BB * AA];
__device__ float g_f0x[BB * HH];
__device__ float g_f0c[BB * HH];
__device__ float g_f1x[BB * OO];
__device__ float g_f1c[BB * OO];
__device__ unsigned g_cnt = 0;
__device__ unsigned g_gen = 0;

__device__ __forceinline__ float sigf(float x) { return 1.0f / (1.0f + __expf(-x)); }

// ---------------- packed f32x2 helpers ----------------
__device__ __forceinline__ unsigned long long pk2(float a) {
    unsigned long long r;
    asm("mov.b64 %0, {%1, %1};" : "=l"(r) : "f"(a));
    return r;
}
__device__ __forceinline__ void fma2(unsigned long long& d,
                                     unsigned long long a, unsigned long long b) {
    asm("fma.rn.f32x2 %0, %1, %2, %0;" : "+l"(d) : "l"(a), "l"(b));
}
__device__ __forceinline__ float2 upk(unsigned long long v) {
    float2 r;
    asm("mov.b64 {%0, %1}, %2;" : "=f"(r.x), "=f"(r.y) : "l"(v));
    return r;
}

// ---------------- grid-wide barrier ----------------
__device__ __forceinline__ void gsync() {
    __syncthreads();
    if (threadIdx.x == 0) {
        unsigned gen = *(volatile unsigned*)&g_gen;
        __threadfence();                       // release
        if (atomicInc(&g_cnt, NB - 1) == NB - 1) {
            atomicAdd(&g_gen, 1);
        } else {
            while (*(volatile unsigned*)&g_gen == gen) { __nanosleep(32); }
        }
        __threadfence();                       // acquire (L1 invalidate)
    }
    __syncthreads();
}

// ---------------- GEMM stage (f32x2 inner) ----------------
// C[64 x N] = A[64 x K] @ W[N x K]^T, tiles 64 x TN (TN = NP*64), K chunk KCH.
// A = virtual concat of up to 4 sources; optional A-scale = sum of 2 ahe partials.
// W = 2-way virtual concat. Partial output: outP[kc*strideP + r*N + c]
// (+ biasP at kc==0 when given).
template<int NP>
__device__ void gemm_stage(float* sA, float* sW,
    int nunits, int ntiles, int KCH,
    const float* __restrict__ A0, const float* __restrict__ A1,
    const float* __restrict__ A2, const float* __restrict__ A3,
    int s0, int s1, int s2, int s3, int b0, int b1, int b2,
    const float* __restrict__ scP, int sstr,
    const float* __restrict__ W0, int w0s,
    const float* __restrict__ W1, int w1s, int wsplit,
    const float* __restrict__ biasP,
    float* __restrict__ outP, int strideP, int N)
{
    constexpr int TN = NP * 64;
    const int tid = threadIdx.x;
    const int tm = tid >> 5;          // warp id: rows tm*8..tm*8+7
    const int tn = tid & 31;          // lane: col groups

    for (int u = blockIdx.x; u < nunits; u += NB) {
        const int tile  = u % ntiles;
        const int kc    = u / ntiles;
        const int kbase = kc * KCH;

        const float* Asrc; int Astr, aloc;
        if      (kbase < b0) { Asrc = A0; Astr = s0; aloc = kbase;      }
        else if (kbase < b1) { Asrc = A1; Astr = s1; aloc = kbase - b0; }
        else if (kbase < b2) { Asrc = A2; Astr = s2; aloc = kbase - b1; }
        else                 { Asrc = A3; Astr = s3; aloc = kbase - b2; }
        const float* Wsrc; int Wstr, wloc;
        if (kbase < wsplit) { Wsrc = W0; Wstr = w0s; wloc = kbase; }
        else                { Wsrc = W1; Wstr = w1s; wloc = kbase - wsplit; }

        unsigned long long acc[8][NP];
#pragma unroll
        for (int i = 0; i < 8; i++)
#pragma unroll
            for (int j = 0; j < NP; j++) acc[i][j] = 0ULL;

        for (int k0 = 0; k0 < KCH; k0 += 32) {
            __syncthreads();
            // stage A: 64 rows x 32 k, float4 per thread (2 iters), STS.128 conflict-free
#pragma unroll
            for (int it = 0; it < 2; it++) {
                int f = it * 256 + tid;
                int b = f & 63, k4 = (f >> 6) << 2;
                float4 v = *(const float4*)(Asrc + b * Astr + aloc + k0 + k4);
                if (scP) {
                    const float* sc0 = scP + b * sstr + kbase + k0 + k4;
                    float4 p0 = *(const float4*)sc0;
                    float4 p1 = *(const float4*)(sc0 + OFFA);
                    v.x *= p0.x + p1.x; v.y *= p0.y + p1.y;
                    v.z *= p0.z + p1.z; v.w *= p0.w + p1.w;
                }
                *(float4*)(sA + b * 36 + k4) = v;
            }
            // stage W: TN cols x 32 k -> k-major; scattered float4 GMEM reads,
            // consecutive-lane STS.32 (conflict-free)
#pragma unroll
            for (int it = 0; it < TN / 32; it++) {
                int f = it * 256 + tid;
                int n = f & (TN - 1);
                int k4 = (f / TN) << 2;
                float4 v = *(const float4*)(Wsrc + (size_t)(tile * TN + n) * Wstr + wloc + k0 + k4);
                sW[(k4 + 0) * TN + n] = v.x;
                sW[(k4 + 1) * TN + n] = v.y;
                sW[(k4 + 2) * TN + n] = v.z;
                sW[(k4 + 3) * TN + n] = v.w;
            }
            __syncthreads();
#pragma unroll 8
            for (int k = 0; k < 32; k++) {
                unsigned long long w[NP];
                {
                    ulonglong2 t0 = *(const ulonglong2*)(sW + k * TN + tn * 4);
                    w[0] = t0.x; w[1] = t0.y;
                    if (NP == 4) {
                        ulonglong2 t1 = *(const ulonglong2*)(sW + k * TN + 128 + tn * 4);
                        w[2] = t1.x; w[3] = t1.y;
                    }
                }
#pragma unroll
                for (int i = 0; i < 8; i++) {
                    unsigned long long a2 = pk2(sA[(tm * 8 + i) * 36 + k]);
#pragma unroll
                    for (int j = 0; j < NP; j++) fma2(acc[i][j], a2, w[j]);
                }
            }
        }

        // epilogue: partial store (+bias on chunk 0)
        float* dst = outP + (size_t)kc * strideP;
#pragma unroll
        for (int g = 0; g < NP / 2; g++) {
            const int col = tile * TN + g * 128 + tn * 4;
            float4 bv = make_float4(0.f, 0.f, 0.f, 0.f);
            if (biasP && kc == 0) bv = *(const float4*)(biasP + col);
#pragma unroll
            for (int i = 0; i < 8; i++) {
                int r = tm * 8 + i;
                float2 lo = upk(acc[i][2 * g]);
                float2 hi = upk(acc[i][2 * g + 1]);
                float4 v = make_float4(lo.x + bv.x, lo.y + bv.y, hi.x + bv.z, hi.y + bv.w);
                *(float4*)(dst + (size_t)r * N + col) = v;
            }
        }
    }
}

// ---------------- adapt (plain LSTM) cell ----------------
__device__ void adapt_cell(const float* __restrict__ part, int nch,
                           const float* __restrict__ bih, const float* __restrict__ bhh,
                           float* __restrict__ xs, float* __restrict__ cs)
{
    int idx = blockIdx.x * 256 + threadIdx.x;
    if (idx < BB * AA) {
        int b = idx >> 7, a = idx & 127;
        const float* p = part + b * 512 + a;
        float g0 = bih[a]       + bhh[a];
        float g1 = bih[128 + a] + bhh[128 + a];
        float g2 = bih[256 + a] + bhh[256 + a];
        float g3 = bih[384 + a] + bhh[384 + a];
        for (int kc = 0; kc < nch; kc++, p += 64 * 512) {
            g0 += p[0]; g1 += p[128]; g2 += p[256]; g3 += p[384];
        }
        float i = sigf(g0), f = sigf(g1), gg = tanhf(g2), o = sigf(g3);
        float c2 = f * cs[idx] + i * gg;
        cs[idx] = c2;
        xs[idx] = o * tanhf(c2);
    }
}

// ---------------- adaptive (f) cell ----------------
__device__ void fcell_cell(int idx0, int stride,
                           const float* __restrict__ part, int nx, int ntot,
                           const float* __restrict__ fb, const float* __restrict__ ahe,
                           int psz, int ninp,
                           float* __restrict__ xs, float* __restrict__ cs,
                           float* __restrict__ out)
{
    for (int idx = idx0; idx < BB * 1024; idx += stride) {
        int b = idx >> 10, h = idx & 1023;
        const float* ab0 = ahe + (size_t)b * psz;
        const float* ab1 = ab0 + OFFA;
        float g[4];
#pragma unroll
        for (int q = 0; q < 4; q++) {
            int n = (q << 10) + h;
            const float* p = part + b * 4096 + n;
            float px = 0.0f, ph = 0.0f;
            int kc = 0;
            for (; kc < nx; kc++)   px += p[kc * (64 * 4096)];
            for (; kc < ntot; kc++) ph += p[kc * (64 * 4096)];
            float sig_ = ab0[ninp + 1024 + n] + ab1[ninp + 1024 + n];
            float shg  = ab0[ninp + 5120 + n] + ab1[ninp + 5120 + n];
            float sb   = ab0[ninp + 9216 + n] + ab1[ninp + 9216 + n];
            g[q] = px * sig_ + ph * shg + fb[n] * sb;
        }
        float i = sigf(g[0]), f = sigf(g[1]), gg = tanhf(g[2]), o = sigf(g[3]);
        float c2 = f * cs[idx] + i * gg;
        float hx = o * tanhf(c2);
        cs[idx] = c2;
        xs[idx] = hx;
        if (out) out[idx] = hx;
    }
}

// ---------------- persistent kernel ----------------
__global__ void __launch_bounds__(256, 2) alstm_persist(
    const float* __restrict__ x,
    const float* __restrict__ a_wih0, const float* __restrict__ a_whh0,
    const float* __restrict__ a_bih0, const float* __restrict__ a_bhh0,
    const float* __restrict__ p_w0,   const float* __restrict__ p_b0,
    const float* __restrict__ f_wih0, const float* __restrict__ f_whh0,
    const float* __restrict__ f_b0,
    const float* __restrict__ a_wih1, const float* __restrict__ a_whh1,
    const float* __restrict__ a_bih1, const float* __restrict__ a_bhh1,
    const float* __restrict__ p_w1,   const float* __restrict__ p_b1,
    const float* __restrict__ f_wih1, const float* __restrict__ f_whh1,
    const float* __restrict__ f_b1,
    float* __restrict__ out)
{
    __shared__ __align__(16) float sA[64 * 36];
    __shared__ __align__(16) float sW[32 * 256];

    const int gtid = blockIdx.x * 256 + threadIdx.x;

    for (int i = gtid; i < BB * AA; i += NB * 256) {
        g_a0x[i] = 0.0f; g_a0c[i] = 0.0f; g_a1x[i] = 0.0f; g_a1c[i] = 0.0f;
    }
    for (int i = gtid; i < BB * HH; i += NB * 256) {
        g_f0x[i] = 0.0f; g_f0c[i] = 0.0f; g_f1x[i] = 0.0f; g_f1c[i] = 0.0f;
    }
    gsync();

    // S1 for t=0 (standalone): A=[xt|f0x|a1x|a0x], K=1536, N=512, KCH=32 -> 48x4=192 units
    gemm_stage<2>(sA, sW, 192, 4, 32,
        x, g_f0x, g_a1x, g_a0x, II, HH, AA, AA, 256, 1280, 1408,
        nullptr, 0,
        a_wih0, 1408, a_whh0, 128, 1408,
        nullptr, g_partA, 64 * 512, 512);
    gsync();

    for (int t = 0; t < TT; t++) {
        const float* xt = x + (size_t)t * BB * II;

        adapt_cell(g_partA, 48, a_bih0, a_bhh0, g_a0x, g_a0c);
        gsync();

        // S2: ahe0 partials (2 x K=64), bias on kc0. N=13568 -> 106x2=212 units
        gemm_stage<2>(sA, sW, 212, 106, 64,
            g_a0x, g_a0x, g_a0x, g_a0x, AA, AA, AA, AA, BIGB, BIGB, BIGB,
            nullptr, 0,
            p_w0, AA, p_w0, AA, BIGB,
            p_b0, g_aheP, OFFA, PSZ0);
        gsync();

        // S3: fcell0 GEMM. A=[xt*a_x|f0x*a_h], K=1280, KCH=64, N=4096 -> 32x20=640 units
        gemm_stage<2>(sA, sW, 640, 32, 64,
            xt, g_f0x, g_f0x, g_f0x, II, HH, HH, HH, 256, BIGB, BIGB,
            g_aheP, PSZ0,
            f_wih0, II, f_whh0, HH, 256,
            nullptr, g_partF, 64 * 4096, 4096);
        gsync();

        fcell_cell(gtid, NB * 256, g_partF, 4, 20, f_b0, g_aheP, PSZ0, II,
                   g_f0x, g_f0c, nullptr);
        gsync();

        // S4: adapt1 GEMM. A=[f0x|f1x|a0x|a1x], K=2304, KCH=64, N=512 -> 4x36=144 units
        gemm_stage<2>(sA, sW, 144, 4, 64,
            g_f0x, g_f1x, g_a0x, g_a1x, HH, OO, AA, AA, 1024, 2048, 2176,
            nullptr, 0,
            a_wih1, 2176, a_whh1, 128, 2176,
            nullptr, g_partA, 64 * 512, 512);
        gsync();

        adapt_cell(g_partA, 36, a_bih1, a_bhh1, g_a1x, g_a1c);
        gsync();

        // S5: ahe1 partials. N=14336 -> 112x2=224 units
        gemm_stage<2>(sA, sW, 224, 112, 64,
            g_a1x, g_a1x, g_a1x, g_a1x, AA, AA, AA, AA, BIGB, BIGB, BIGB,
            nullptr, 0,
            p_w1, AA, p_w1, AA, BIGB,
            p_b1, g_aheP, OFFA, PSZ1);
        gsync();

        // S6: fcell1 GEMM. A=[f0x*a_x|f1x*a_h], K=2048, KCH=128, TN=256 -> 16x16=256 units
        gemm_stage<4>(sA, sW, 256, 16, 128,
            g_f0x, g_f1x, g_f1x, g_f1x, HH, OO, OO, OO, 1024, BIGB, BIGB,
            g_aheP, PSZ1,
            f_wih1, HH, f_whh1, OO, 1024,
            nullptr, g_partF, 64 * 4096, 4096);
        gsync();

        // merged: fcell1 epilogue (CTAs >= 192) || S1 for t+1 (CTAs < 192)
        // S1 reads xt+1, f0x, a0x, a1x (all stable); writes g_partA (disjoint).
        if (t + 1 < TT) {
            gemm_stage<2>(sA, sW, 192, 4, 32,
                x + (size_t)(t + 1) * BB * II, g_f0x, g_a1x, g_a0x,
                II, HH, AA, AA, 256, 1280, 1408,
                nullptr, 0,
                a_wih0, 1408, a_whh0, 128, 1408,
                nullptr, g_partA, 64 * 512, 512);
        }
        if (blockIdx.x >= 192) {
            fcell_cell((blockIdx.x - 192) * 256 + threadIdx.x, (NB - 192) * 256,
                       g_partF, 8, 16, f_b1, g_aheP, PSZ1, HH,
                       g_f1x, g_f1c, out + (size_t)t * BB * OO);
        }
        gsync();
    }
}

// ---------------- launcher: ONE graph node ----------------
extern "C" void kernel_launch(void* const* d_in, const int* in_sizes, int n_in,
                              void* d_out, int out_size)
{
    alstm_persist<<<NB, 256>>>(
        (const float*)d_in[0],
        (const float*)d_in[1],  (const float*)d_in[2],
        (const float*)d_in[3],  (const float*)d_in[4],
        (const float*)d_in[5],  (const float*)d_in[6],
        (const float*)d_in[7],  (const float*)d_in[8],
        (const float*)d_in[9],
        (const float*)d_in[10], (const float*)d_in[11],
        (const float*)d_in[12], (const float*)d_in[13],
        (const float*)d_in[14], (const float*)d_in[15],
        (const float*)d_in[16], (const float*)d_in[17],
        (const float*)d_in[18],
        (float*)d_out);
}

// round 10
// speedup vs baseline: 1.0130x; 1.0130x over previous
#include <cuda_runtime.h>
#include <math.h>

// ---------------- problem constants ----------------
#define TT 512
#define BB 64
#define II 256
#define HH 1024
#define AA 128
#define OO 1024
#define PSZ0 13568            // I + 13H
#define PSZ1 14336            // H + 13O
#define NB 256                // persistent CTAs (2/SM on 128 SMs; safe residency)
#define BIGB (1 << 30)

// ---------------- device scratch (static, no runtime alloc) ----------------
__device__ float g_partF[16 * 64 * 4096];   // fcell split-K partials (S3:10, S6:16)
__device__ float g_partA[36 * 64 * 512];    // adapt split-K partials (S1:24, S4:36)
__device__ float g_ahe [64 * PSZ1];         // policy output (single buffer, reused L0/L1)
__device__ float g_a0x[BB * AA];
__device__ float g_a0c[BB * AA];
__device__ float g_a1x[BB * AA];
__device__ float g_a1c[BB * AA];
__device__ float g_f0x[BB * HH];
__device__ float g_f0c[BB * HH];
__device__ float g_f1x[BB * OO];
__device__ float g_f1c[BB * OO];
__device__ unsigned g_cnt = 0;
__device__ unsigned g_gen = 0;

__device__ __forceinline__ float sigf(float x) { return 1.0f / (1.0f + __expf(-x)); }

// ---------------- packed f32x2 helpers ----------------
__device__ __forceinline__ unsigned long long pk2(float a) {
    unsigned long long r;
    asm("mov.b64 %0, {%1, %1};" : "=l"(r) : "f"(a));
    return r;
}
__device__ __forceinline__ void fma2(unsigned long long& d,
                                     unsigned long long a, unsigned long long b) {
    asm("fma.rn.f32x2 %0, %1, %2, %0;" : "+l"(d) : "l"(a), "l"(b));
}
__device__ __forceinline__ float2 upk(unsigned long long v) {
    float2 r;
    asm("mov.b64 {%0, %1}, %2;" : "=f"(r.x), "=f"(r.y) : "l"(v));
    return r;
}

// ---------------- grid-wide barrier ----------------
__device__ __forceinline__ void gsync() {
    __syncthreads();
    if (threadIdx.x == 0) {
        unsigned gen = *(volatile unsigned*)&g_gen;
        __threadfence();                       // release
        if (atomicInc(&g_cnt, NB - 1) == NB - 1) {
            atomicAdd(&g_gen, 1);
        } else {
            while (*(volatile unsigned*)&g_gen == gen) { __nanosleep(32); }
        }
        __threadfence();                       // acquire (L1 invalidate)
    }
    __syncthreads();
}

// ---------------- staging prefetch (GMEM -> regs) ----------------
// One 32-k sub-block: A 64x32 (2 float4/thread), W TNx32 (2*NP float4/thread).
// Source resolution at 32-k granularity (all concat boundaries are 32-aligned).
template<int NP>
__device__ __forceinline__ void prefetch_sub(
    int kk, int tid, int tile,
    const float* __restrict__ A0, const float* __restrict__ A1,
    const float* __restrict__ A2, const float* __restrict__ A3,
    int s0, int s1, int s2, int s3, int b0, int b1, int b2,
    const float* __restrict__ scP, int sstr,
    const float* __restrict__ W0, int w0s,
    const float* __restrict__ W1, int w1s, int wsplit,
    float4* pa, float4* pw)
{
    constexpr int TN = NP * 64;
    const float* Asrc; int Astr, aloc;
    if      (kk < b0) { Asrc = A0; Astr = s0; aloc = kk;      }
    else if (kk < b1) { Asrc = A1; Astr = s1; aloc = kk - b0; }
    else if (kk < b2) { Asrc = A2; Astr = s2; aloc = kk - b1; }
    else              { Asrc = A3; Astr = s3; aloc = kk - b2; }
#pragma unroll
    for (int it = 0; it < 2; it++) {
        int f = it * 256 + tid, b = f & 63, k4 = (f >> 6) << 2;
        float4 v = *(const float4*)(Asrc + b * Astr + aloc + k4);
        if (scP) {
            float4 s = *(const float4*)(scP + b * sstr + kk + k4);
            v.x *= s.x; v.y *= s.y; v.z *= s.z; v.w *= s.w;
        }
        pa[it] = v;
    }
    const float* Wsrc; int Wstr, wloc;
    if (kk < wsplit) { Wsrc = W0; Wstr = w0s; wloc = kk; }
    else             { Wsrc = W1; Wstr = w1s; wloc = kk - wsplit; }
#pragma unroll
    for (int it = 0; it < 2 * NP; it++) {
        int f = it * 256 + tid, n = f & (TN - 1), k4 = (f / TN) << 2;
        pw[it] = *(const float4*)(Wsrc + (size_t)(tile * TN + n) * Wstr + wloc + k4);
    }
}

// ---------------- GEMM stage (f32x2, k4-blocked, reg-prefetch pipeline) ----
// C[64 x N] = A[64 x K] @ W[N x K]^T, tiles 64 x TN (TN = NP*64), K chunk KCH.
// Runs on CTAs [cta0, cta0+nctas). Partial -> outP[kc*strideP]; bias on kc==0.
template<int NP>
__device__ void gemm_stage(float* sA, float* sW,
    int cta0, int nctas,
    int nunits, int ntiles, int KCH,
    const float* __restrict__ A0, const float* __restrict__ A1,
    const float* __restrict__ A2, const float* __restrict__ A3,
    int s0, int s1, int s2, int s3, int b0, int b1, int b2,
    const float* __restrict__ scP, int sstr,
    const float* __restrict__ W0, int w0s,
    const float* __restrict__ W1, int w1s, int wsplit,
    const float* __restrict__ biasP,
    float* __restrict__ outP, int strideP, int N)
{
    constexpr int TN = NP * 64;
    const int tid = threadIdx.x;
    const int tm = tid >> 5, tn = tid & 31;
    const int bid = (int)blockIdx.x - cta0;
    if (bid < 0 || bid >= nctas) return;

    for (int u = bid; u < nunits; u += nctas) {
        const int tile = u % ntiles, kc = u / ntiles;
        const int kbase = kc * KCH;

        unsigned long long acc[8][NP];
#pragma unroll
        for (int i = 0; i < 8; i++)
#pragma unroll
            for (int j = 0; j < NP; j++) acc[i][j] = 0ULL;

        float4 pa[2], pw[2 * NP];
        prefetch_sub<NP>(kbase, tid, tile, A0, A1, A2, A3, s0, s1, s2, s3,
                         b0, b1, b2, scP, sstr, W0, w0s, W1, w1s, wsplit, pa, pw);

        for (int k0 = 0; k0 < KCH; k0 += 32) {
            __syncthreads();
            // STS current sub-block
#pragma unroll
            for (int it = 0; it < 2; it++) {
                int f = it * 256 + tid, b = f & 63, k4 = (f >> 6) << 2;
                *(float4*)(sA + b * 36 + k4) = pa[it];
            }
#pragma unroll
            for (int it = 0; it < 2 * NP; it++) {
                int f = it * 256 + tid, n = f & (TN - 1), k4 = (f / TN) << 2;
                sW[(k4 + 0) * TN + n] = pw[it].x;
                sW[(k4 + 1) * TN + n] = pw[it].y;
                sW[(k4 + 2) * TN + n] = pw[it].z;
                sW[(k4 + 3) * TN + n] = pw[it].w;
            }
            // prefetch next sub-block (latency hidden behind compute)
            if (k0 + 32 < KCH)
                prefetch_sub<NP>(kbase + k0 + 32, tid, tile, A0, A1, A2, A3,
                                 s0, s1, s2, s3, b0, b1, b2, scP, sstr,
                                 W0, w0s, W1, w1s, wsplit, pa, pw);
            __syncthreads();
            // compute: k4 blocks of 4
#pragma unroll
            for (int k4 = 0; k4 < 32; k4 += 4) {
                unsigned long long w[4][NP];
#pragma unroll
                for (int kk = 0; kk < 4; kk++) {
                    if (NP == 2) {
                        ulonglong2 t = *(const ulonglong2*)(sW + (k4 + kk) * TN + tn * 4);
                        w[kk][0] = t.x; w[kk][1] = t.y;
                    } else {
                        w[kk][0] = *(const unsigned long long*)(sW + (k4 + kk) * TN + tn * 2);
                    }
                }
#pragma unroll
                for (int i = 0; i < 8; i++) {
                    float4 av = *(const float4*)(sA + (tm * 8 + i) * 36 + k4);
                    unsigned long long a0 = pk2(av.x), a1 = pk2(av.y);
                    unsigned long long a2 = pk2(av.z), a3 = pk2(av.w);
#pragma unroll
                    for (int j = 0; j < NP; j++) {
                        fma2(acc[i][j], a0, w[0][j]);
                        fma2(acc[i][j], a1, w[1][j]);
                        fma2(acc[i][j], a2, w[2][j]);
                        fma2(acc[i][j], a3, w[3][j]);
                    }
                }
            }
        }

        // epilogue
        float* dst = outP + (size_t)kc * strideP;
        if (NP == 2) {
            const int col = tile * TN + tn * 4;
            float4 bv = make_float4(0.f, 0.f, 0.f, 0.f);
            if (biasP && kc == 0) bv = *(const float4*)(biasP + col);
#pragma unroll
            for (int i = 0; i < 8; i++) {
                int r = tm * 8 + i;
                float2 lo = upk(acc[i][0]), hi = upk(acc[i][1]);
                float4 v = make_float4(lo.x + bv.x, lo.y + bv.y, hi.x + bv.z, hi.y + bv.w);
                *(float4*)(dst + (size_t)r * N + col) = v;
            }
        } else {
            const int col = tile * TN + tn * 2;
            float2 bv = make_float2(0.f, 0.f);
            if (biasP && kc == 0) { bv.x = biasP[col]; bv.y = biasP[col + 1]; }
#pragma unroll
            for (int i = 0; i < 8; i++) {
                int r = tm * 8 + i;
                float2 lo = upk(acc[i][0]);
                float2 v = make_float2(lo.x + bv.x, lo.y + bv.y);
                *(float2*)(dst + (size_t)r * N + col) = v;
            }
        }
    }
}

// ---------------- adapt (plain LSTM) cell: 32 CTAs starting at cta0 -------
__device__ void adapt_cell(int cta0,
                           const float* __restrict__ part, int nch,
                           const float* __restrict__ bih, const float* __restrict__ bhh,
                           float* __restrict__ xs, float* __restrict__ cs)
{
    int bid = (int)blockIdx.x - cta0;
    if (bid < 0 || bid >= 32) return;
    int idx = bid * 256 + threadIdx.x;          // 8192 = 64*128
    int b = idx >> 7, a = idx & 127;
    const float* p = part + b * 512 + a;
    float g0 = bih[a]       + bhh[a];
    float g1 = bih[128 + a] + bhh[128 + a];
    float g2 = bih[256 + a] + bhh[256 + a];
    float g3 = bih[384 + a] + bhh[384 + a];
    for (int kc = 0; kc < nch; kc++, p += 64 * 512) {
        g0 += p[0]; g1 += p[128]; g2 += p[256]; g3 += p[384];
    }
    float i = sigf(g0), f = sigf(g1), gg = tanhf(g2), o = sigf(g3);
    float c2 = f * cs[idx] + i * gg;
    cs[idx] = c2;
    xs[idx] = o * tanhf(c2);
}

// ---------------- adaptive (f) cell ----------------
__device__ void fcell_cell(int idx0, int stride,
                           const float* __restrict__ part, int nx, int ntot,
                           const float* __restrict__ fb, const float* __restrict__ ahe,
                           int psz, int ninp,
                           float* __restrict__ xs, float* __restrict__ cs,
                           float* __restrict__ out)
{
    for (int idx = idx0; idx < BB * 1024; idx += stride) {
        int b = idx >> 10, h = idx & 1023;
        const float* ab = ahe + (size_t)b * psz;
        float g[4];
#pragma unroll
        for (int q = 0; q < 4; q++) {
            int n = (q << 10) + h;
            const float* p = part + b * 4096 + n;
            float px = 0.0f, ph = 0.0f;
            int kc = 0;
            for (; kc < nx; kc++)   px += p[kc * (64 * 4096)];
            for (; kc < ntot; kc++) ph += p[kc * (64 * 4096)];
            g[q] = px * ab[ninp + 1024 + n] + ph * ab[ninp + 5120 + n]
                 + fb[n] * ab[ninp + 9216 + n];
        }
        float i = sigf(g[0]), f = sigf(g[1]), gg = tanhf(g[2]), o = sigf(g[3]);
        float c2 = f * cs[idx] + i * gg;
        float hx = o * tanhf(c2);
        cs[idx] = c2;
        xs[idx] = hx;
        if (out) out[idx] = hx;
    }
}

// ---------------- persistent kernel ----------------
__global__ void __launch_bounds__(256, 2) alstm_persist(
    const float* __restrict__ x,
    const float* __restrict__ a_wih0, const float* __restrict__ a_whh0,
    const float* __restrict__ a_bih0, const float* __restrict__ a_bhh0,
    const float* __restrict__ p_w0,   const float* __restrict__ p_b0,
    const float* __restrict__ f_wih0, const float* __restrict__ f_whh0,
    const float* __restrict__ f_b0,
    const float* __restrict__ a_wih1, const float* __restrict__ a_whh1,
    const float* __restrict__ a_bih1, const float* __restrict__ a_bhh1,
    const float* __restrict__ p_w1,   const float* __restrict__ p_b1,
    const float* __restrict__ f_wih1, const float* __restrict__ f_whh1,
    const float* __restrict__ f_b1,
    float* __restrict__ out)
{
    __shared__ __align__(16) float sA[64 * 36];
    __shared__ __align__(16) float sW[32 * 128];

    const int gtid = blockIdx.x * 256 + threadIdx.x;

    for (int i = gtid; i < BB * AA; i += NB * 256) {
        g_a0x[i] = 0.0f; g_a0c[i] = 0.0f; g_a1x[i] = 0.0f; g_a1c[i] = 0.0f;
    }
    for (int i = gtid; i < BB * HH; i += NB * 256) {
        g_f0x[i] = 0.0f; g_f0c[i] = 0.0f; g_f1x[i] = 0.0f; g_f1c[i] = 0.0f;
    }
    gsync();

    // S1(0): A=[x0|f0x|a1x|a0x], K=1536, KCH=64 -> 24 chunks x 4 tiles = 96 units
    gemm_stage<2>(sA, sW, 0, NB, 96, 4, 64,
        x, g_f0x, g_a1x, g_a0x, II, HH, AA, AA, 256, 1280, 1408,
        nullptr, 0, a_wih0, 1408, a_whh0, 128, 1408,
        nullptr, g_partA, 64 * 512, 512);
    gsync();
    adapt_cell(0, g_partA, 24, a_bih0, a_bhh0, g_a0x, g_a0c);
    gsync();

    for (int t = 0; t < TT; t++) {
        const float* xt = x + (size_t)t * BB * II;

        // A: S2 ahe0 = a0x @ p_w0^T + p_b0, full K=128, TN=64 -> 212 units
        gemm_stage<1>(sA, sW, 0, NB, 212, 212, 128,
            g_a0x, g_a0x, g_a0x, g_a0x, AA, AA, AA, AA, BIGB, BIGB, BIGB,
            nullptr, 0, p_w0, AA, p_w0, AA, BIGB,
            p_b0, g_ahe, 0, PSZ0);
        gsync();

        // B: S3 fcell0 GEMM. A=[xt*a_x|f0x*a_h], K=1280, KCH=128, TN=64 -> 640 units
        gemm_stage<1>(sA, sW, 0, NB, 640, 64, 128,
            xt, g_f0x, g_f0x, g_f0x, II, HH, HH, HH, 256, BIGB, BIGB,
            g_ahe, PSZ0, f_wih0, II, f_whh0, HH, 256,
            nullptr, g_partF, 64 * 4096, 4096);
        gsync();

        // C: fcell0 (full grid). chunks 0-1 = x, 2-9 = h
        fcell_cell(gtid, NB * 256, g_partF, 2, 10, f_b0, g_ahe, PSZ0, II,
                   g_f0x, g_f0c, nullptr);
        gsync();

        // D: S4 adapt1 GEMM. A=[f0x|f1x|a0x|a1x], K=2304, KCH=64 -> 36 x 4 = 144 units
        gemm_stage<2>(sA, sW, 0, NB, 144, 4, 64,
            g_f0x, g_f1x, g_a0x, g_a1x, HH, OO, AA, AA, 1024, 2048, 2176,
            nullptr, 0, a_wih1, 2176, a_whh1, 128, 2176,
            nullptr, g_partA, 64 * 512, 512);
        gsync();

        // E: adapt1
        adapt_cell(0, g_partA, 36, a_bih1, a_bhh1, g_a1x, g_a1c);
        gsync();

        // F: S5 (CTAs 0-111) || S1(t+1) (CTAs 112-207)
        gemm_stage<2>(sA, sW, 0, 112, 112, 112, 128,
            g_a1x, g_a1x, g_a1x, g_a1x, AA, AA, AA, AA, BIGB, BIGB, BIGB,
            nullptr, 0, p_w1, AA, p_w1, AA, BIGB,
            p_b1, g_ahe, 0, PSZ1);
        if (t + 1 < TT)
            gemm_stage<2>(sA, sW, 112, 96, 96, 4, 64,
                x + (size_t)(t + 1) * BB * II, g_f0x, g_a1x, g_a0x,
                II, HH, AA, AA, 256, 1280, 1408,
                nullptr, 0, a_wih0, 1408, a_whh0, 128, 1408,
                nullptr, g_partA, 64 * 512, 512);
        gsync();

        // G: S6 fcell1 GEMM. A=[f0x*a_x|f1x*a_h], K=2048, KCH=128, TN=128 -> 512 units
        gemm_stage<2>(sA, sW, 0, NB, 512, 32, 128,
            g_f0x, g_f1x, g_f1x, g_f1x, HH, OO, OO, OO, 1024, BIGB, BIGB,
            g_ahe, PSZ1, f_wih1, HH, f_whh1, OO, 1024,
            nullptr, g_partF, 64 * 4096, 4096);
        gsync();

        // H: fcell1 (CTAs 0-223) || adapt0(t+1) (CTAs 224-255)
        if (blockIdx.x < 224) {
            fcell_cell(blockIdx.x * 256 + threadIdx.x, 224 * 256,
                       g_partF, 8, 16, f_b1, g_ahe, PSZ1, HH,
                       g_f1x, g_f1c, out + (size_t)t * BB * OO);
        } else if (t + 1 < TT) {
            adapt_cell(224, g_partA, 24, a_bih0, a_bhh0, g_a0x, g_a0c);
        }
        gsync();
    }
}

// ---------------- launcher: ONE graph node ----------------
extern "C" void kernel_launch(void* const* d_in, const int* in_sizes, int n_in,
                              void* d_out, int out_size)
{
    alstm_persist<<<NB, 256>>>(
        (const float*)d_in[0],
        (const float*)d_in[1],  (const float*)d_in[2],
        (const float*)d_in[3],  (const float*)d_in[4],
        (const float*)d_in[5],  (const float*)d_in[6],
        (const float*)d_in[7],  (const float*)d_in[8],
        (const float*)d_in[9],
        (const float*)d_in[10], (const float*)d_in[11],
        (const float*)d_in[12], (const float*)d_in[13],
        (const float*)d_in[14], (const float*)d_in[15],
        (const float*)d_in[16], (const float*)d_in[17],
        (const float*)d_in[18],
        (float*)d_out);
}